// round 10
// baseline (speedup 1.0000x reference)
#include <cuda_runtime.h>
#include <cuda_bf16.h>
#include <cstdint>

#define NEGV  (-1e20f)
#define Bsz   128
#define TU    256
#define TB    128
#define TP    64
#define HH    512
#define VV    3000
#define VOOVc 3400

typedef __nv_bfloat16 bf16;

// ---------------- fp32 scratch ----------------
__device__ float g_q[Bsz*HH];
__device__ float g_scores[Bsz*(TU+TB+TP)];
__device__ float g_gi[Bsz*1536];
__device__ float g_gh[Bsz*1536];
__device__ float g_hnew[Bsz*HH];
__device__ float g_gen[Bsz*VV];
__device__ float g_cpraw[Bsz*TB];

// ---------------- bf16 scratch ----------------
__device__ __align__(16) bf16 gb_usdx[Bsz*TU*HH];
__device__ __align__(16) bf16 gb_bspn[Bsz*TB*HH];
__device__ __align__(16) bf16 gb_pv  [Bsz*TP*HH];
__device__ __align__(16) bf16 gb_attnW[HH*2*HH];
__device__ __align__(16) bf16 gb_Wc  [HH*HH];
__device__ __align__(16) bf16 gb_Wg  [3072*HH];
__device__ __align__(16) bf16 gb_Wih [1536*2080];
__device__ __align__(16) bf16 gb_Whh [1536*HH];
__device__ __align__(16) bf16 gb_h0  [Bsz*HH];
__device__ __align__(16) bf16 gb_x   [Bsz*2080];
__device__ __align__(16) bf16 gb_hnew[Bsz*HH];

// ==================== helpers ====================
__device__ __forceinline__ void cpa16(unsigned d, const void* s) {
    asm volatile("cp.async.cg.shared.global [%0], [%1], 16;" :: "r"(d), "l"(s));
}
__device__ __forceinline__ void ldsm4(unsigned* r, unsigned a) {
    asm volatile("ldmatrix.sync.aligned.m8n8.x4.shared.b16 {%0,%1,%2,%3}, [%4];"
                 : "=r"(r[0]), "=r"(r[1]), "=r"(r[2]), "=r"(r[3]) : "r"(a));
}
__device__ __forceinline__ float tanh_fast(float x) {
    float y;
    asm("tanh.approx.f32 %0, %1;" : "=f"(y) : "f"(x));
    return y;
}

// ==================== megacvt ====================
#define C_USDX  (Bsz*TU*HH/4)
#define C_BSPN  (C_USDX + Bsz*TB*HH/4)
#define C_PV    (C_BSPN + Bsz*TP*HH/4)
#define C_AW    (C_PV   + HH*2*HH/4)
#define C_WC    (C_AW   + HH*HH/4)
#define C_WG    (C_WC   + 3072*HH/4)
#define C_WIH   (C_WG   + 1536*2080/4)
#define C_WHH   (C_WIH  + 1536*HH/4)
#define C_H0    (C_WHH  + Bsz*HH/4)
#define C_Q     (C_H0   + Bsz*HH/4)
#define C_GEN   (C_Q    + Bsz*VV/4)
#define C_ZS    (C_GEN  + Bsz*(TU+TB+TP)/4)
#define C_ZC    (C_ZS   + Bsz*TB/4)
#define C_ZGI   (C_ZC   + Bsz*1536/4)
#define C_ZGH   (C_ZGI  + Bsz*1536/4)

__device__ __forceinline__ void cv4(const float* __restrict__ s, bf16* __restrict__ d, int i)
{
    const float4 v = *(const float4*)(s + 4*(size_t)i);
    __nv_bfloat162 lo = __floats2bfloat162_rn(v.x, v.y);
    __nv_bfloat162 hi = __floats2bfloat162_rn(v.z, v.w);
    *(uint2*)(d + 4*(size_t)i) = make_uint2(*(unsigned*)&lo, *(unsigned*)&hi);
}

__global__ __launch_bounds__(256)
void megacvt(const float* __restrict__ usdx, const float* __restrict__ bspn,
             const float* __restrict__ pv,   const float* __restrict__ aw,
             const float* __restrict__ wc,   const float* __restrict__ wg,
             const float* __restrict__ wih,  const float* __restrict__ whh,
             const float* __restrict__ h0,   const float* __restrict__ attnb,
             const float* __restrict__ wgb)
{
    const int stride = gridDim.x * blockDim.x;
    for (int i = blockIdx.x * blockDim.x + threadIdx.x; i < C_ZGH; i += stride) {
        if (i < C_USDX)      cv4(usdx, gb_usdx, i);
        else if (i < C_BSPN) cv4(bspn, gb_bspn, i - C_USDX);
        else if (i < C_PV)   cv4(pv,   gb_pv,   i - C_BSPN);
        else if (i < C_AW)   cv4(aw,   gb_attnW,i - C_PV);
        else if (i < C_WC)   cv4(wc,   gb_Wc,   i - C_AW);
        else if (i < C_WG) {
            const int j = i - C_WC;
            if (4*j < VV*HH) cv4(wg, gb_Wg, j);
            else *(uint2*)(gb_Wg + 4*(size_t)j) = make_uint2(0u, 0u);
        }
        else if (i < C_WIH)  cv4(wih, gb_Wih, i - C_WG);
        else if (i < C_WHH)  cv4(whh, gb_Whh, i - C_WIH);
        else if (i < C_H0)   cv4(h0,  gb_h0,  i - C_WHH);
        else if (i < C_Q) {
            const int j = (i - C_H0) * 4;
            *(float4*)(g_q + j) = *(const float4*)(attnb + (j & (HH-1)));
        }
        else if (i < C_GEN) {
            const int j = (i - C_Q) * 4;
            *(float4*)(g_gen + j) = *(const float4*)(wgb + (j % VV));
        }
        else if (i < C_ZS)  *(float4*)(g_scores + (i - C_GEN)*4) = make_float4(0,0,0,0);
        else if (i < C_ZC)  *(float4*)(g_cpraw  + (i - C_ZS)*4)  = make_float4(0,0,0,0);
        else if (i < C_ZGI) *(float4*)(g_gi     + (i - C_ZC)*4)  = make_float4(0,0,0,0);
        else                *(float4*)(g_gh     + (i - C_ZGI)*4) = make_float4(0,0,0,0);
    }
}

// =====================================================================
// Fused-score GEMM, K-tile 64, 3-stage cp.async, ldmatrix, tanh.approx.
// Tile 128x128, K%64==0. sOut[m] += sum_n dvec[b,n]*tanh(acc+qadd[b,n]), b=m/T.
// =====================================================================
#define SPADK 72
#define SSTGB (128*SPADK*2)   // 18432 B per stage per matrix
#define SSMEM (6*SSTGB)       // 110592 B

__device__ __forceinline__ void score_core(
    const bf16* __restrict__ A, int lda,
    const bf16* __restrict__ Bw, int ldb,
    int K, int m0, int n0,
    const float* __restrict__ qadd, int qstride,
    const float* __restrict__ dvec, int dstride,
    float* __restrict__ sOut, int T, bf16* smem)
{
    const int tid = threadIdx.x, lane = tid & 31, wid = tid >> 5;
    const int wm = wid >> 2, wn = wid & 3;
    const int g = lane >> 2, tig = lane & 3;
    const unsigned sbase = (unsigned)__cvta_generic_to_shared(smem);

    // cp.async mapping: thread -> row = tid>>1, half = tid&1, 4 chunks of 16B
    const int crow = tid >> 1, chalf = tid & 1;
    const bf16* aS = A  + (size_t)(m0 + crow) * lda + chalf*32;
    const bf16* bS = Bw + (size_t)(n0 + crow) * ldb + chalf*32;
    const unsigned co = crow * (SPADK*2) + chalf*64;

    // fragment bases
    const unsigned aF = sbase + ((wm*64 + (lane&15)) * SPADK + ((lane>>4)*8)) * 2;
    const unsigned bF = sbase + 3*SSTGB +
        ((wn*32 + ((lane>>4)*8) + (lane&7)) * SPADK + (((lane>>3)&1)*8)) * 2;

    float acc[4][4][4];
#pragma unroll
    for (int i = 0; i < 4; i++)
#pragma unroll
        for (int j = 0; j < 4; j++)
#pragma unroll
            for (int c = 0; c < 4; c++) acc[i][j][c] = 0.f;

    const int KT = K >> 6;

    // prologue: stages 0,1
#pragma unroll
    for (int p = 0; p < 2; p++) {
        const int kk = p << 6;
        const unsigned as = sbase + p*SSTGB, bs = sbase + 3*SSTGB + p*SSTGB;
#pragma unroll
        for (int i = 0; i < 4; i++) {
            cpa16(as + co + i*16, aS + kk + i*8);
            cpa16(bs + co + i*16, bS + kk + i*8);
        }
        asm volatile("cp.async.commit_group;");
    }

    int st = 0, stp = 2;
    for (int kt = 0; kt < KT; kt++) {
        asm volatile("cp.async.wait_group 1;");
        __syncthreads();
        if (kt + 2 < KT) {
            const int kk = (kt + 2) << 6;
            const unsigned as = sbase + stp*SSTGB, bs = sbase + 3*SSTGB + stp*SSTGB;
#pragma unroll
            for (int i = 0; i < 4; i++) {
                cpa16(as + co + i*16, aS + kk + i*8);
                cpa16(bs + co + i*16, bS + kk + i*8);
            }
        }
        asm volatile("cp.async.commit_group;");

        const unsigned aB = aF + st * SSTGB;
        const unsigned bB = bF + st * SSTGB;
#pragma unroll
        for (int ks = 0; ks < 4; ks++) {
            unsigned afr[4][4], bfr[4][2];
#pragma unroll
            for (int mf = 0; mf < 4; mf++)
                ldsm4(afr[mf], aB + mf * (16*SPADK*2) + ks * 32);
#pragma unroll
            for (int p = 0; p < 2; p++) {
                unsigned r[4];
                ldsm4(r, bB + p * (16*SPADK*2) + ks * 32);
                bfr[2*p][0] = r[0]; bfr[2*p][1] = r[1];
                bfr[2*p+1][0] = r[2]; bfr[2*p+1][1] = r[3];
            }
#pragma unroll
            for (int mf = 0; mf < 4; mf++)
#pragma unroll
                for (int nf = 0; nf < 4; nf++) {
                    asm volatile(
                        "mma.sync.aligned.m16n8k16.row.col.f32.bf16.bf16.f32 "
                        "{%0,%1,%2,%3},{%4,%5,%6,%7},{%8,%9},{%0,%1,%2,%3};"
                        : "+f"(acc[mf][nf][0]), "+f"(acc[mf][nf][1]),
                          "+f"(acc[mf][nf][2]), "+f"(acc[mf][nf][3])
                        : "r"(afr[mf][0]), "r"(afr[mf][1]), "r"(afr[mf][2]), "r"(afr[mf][3]),
                          "r"(bfr[nf][0]), "r"(bfr[nf][1]));
                }
        }
        st = (st == 2) ? 0 : st + 1;
        stp = (stp == 2) ? 0 : stp + 1;
    }

    // fused epilogue
#pragma unroll
    for (int mf = 0; mf < 4; mf++)
#pragma unroll
        for (int rr = 0; rr < 2; rr++) {
            const int m = m0 + wm*64 + mf*16 + g + rr*8;
            const int b = m / T;
            const float* q  = qadd + (size_t)b * qstride;
            const float* dv = dvec + (size_t)b * dstride;
            float s = 0.f;
#pragma unroll
            for (int nf = 0; nf < 4; nf++) {
                const int n = n0 + wn*32 + nf*8 + 2*tig;
                s += dv[n]   * tanh_fast(acc[mf][nf][rr*2]   + q[n]);
                s += dv[n+1] * tanh_fast(acc[mf][nf][rr*2+1] + q[n+1]);
            }
            s += __shfl_xor_sync(0xffffffffu, s, 1);
            s += __shfl_xor_sync(0xffffffffu, s, 2);
            if (tig == 0) atomicAdd(&sOut[m], s);
        }
}

// batched over all three encoders
__global__ __launch_bounds__(256, 2)
void score_batch(const float* __restrict__ vw)
{
    extern __shared__ bf16 smem_sb[];
    const int by = blockIdx.y;
    const bf16* A; float* sOut; int T, m0;
    if (by < 256)      { A = gb_usdx; sOut = g_scores;               T = TU; m0 = by*128; }
    else if (by < 384) { A = gb_bspn; sOut = g_scores + Bsz*TU;      T = TB; m0 = (by-256)*128; }
    else               { A = gb_pv;   sOut = g_scores + Bsz*(TU+TB); T = TP; m0 = (by-384)*128; }
    score_core(A, HH, gb_attnW + HH, 2*HH, HH, m0, blockIdx.x * 128,
               g_q, HH, vw, 0, sOut, T, smem_sb);
}

// generic wrapper (cp_raw)
__global__ __launch_bounds__(256, 2)
void score_gen(const bf16* __restrict__ A, int lda,
               const bf16* __restrict__ Bw, int ldb, int K,
               const float* __restrict__ qadd, int qstride,
               const float* __restrict__ dvec, int dstride,
               float* __restrict__ sOut, int T)
{
    extern __shared__ bf16 smem_sg[];
    score_core(A, lda, Bw, ldb, K, blockIdx.y * 128, blockIdx.x * 128,
               qadd, qstride, dvec, dstride, sOut, T, smem_sg);
}

// =====================================================================
// HMMA GEMM (small dense cases, K%32==0): C += A@B^T via atomics, split-K
// =====================================================================
#define PADK 40
#define STGB (128*PADK*2)
#define SMEMB (6*STGB)

__global__ __launch_bounds__(256)
void mma_gemm2(const bf16* __restrict__ A, int lda,
               const bf16* __restrict__ Bw, int ldb,
               float* __restrict__ C, int ldc,
               int N, int K)
{
    extern __shared__ bf16 smemg[];
    const int koff = blockIdx.z * K;
    const bf16* Ab = A + koff;
    const bf16* Bb = Bw + koff;
    const int tid = threadIdx.x, lane = tid & 31, wid = tid >> 5;
    const int wm = wid >> 2, wn = wid & 3;
    const int g = lane >> 2, tig = lane & 3;
    const int m0 = blockIdx.y * 128, n0 = blockIdx.x * 128;
    const unsigned sbase = (unsigned)__cvta_generic_to_shared(smemg);

    const int crow = tid >> 2, ci = tid & 3;
    const bf16* aS0 = Ab + (size_t)(m0 + crow) * lda + ci*8;
    const bf16* aS1 = aS0 + (size_t)64 * lda;
    const bf16* bS0 = Bb + (size_t)(n0 + crow) * ldb + ci*8;
    const bf16* bS1 = bS0 + (size_t)64 * ldb;
    const unsigned o0 = (crow * PADK + ci*8) * 2;
    const unsigned o1 = o0 + 64*PADK*2;

    const unsigned aF = sbase + ((wm*64 + (lane&15)) * PADK + ((lane>>4)*8)) * 2;
    const unsigned bF = sbase + 3*STGB +
        ((wn*32 + ((lane>>4)*8) + (lane&7)) * PADK + (((lane>>3)&1)*8)) * 2;

    float acc[4][4][4];
#pragma unroll
    for (int i = 0; i < 4; i++)
#pragma unroll
        for (int j = 0; j < 4; j++)
#pragma unroll
            for (int c = 0; c < 4; c++) acc[i][j][c] = 0.f;

    const int KT = K >> 5;
#pragma unroll
    for (int p = 0; p < 2; p++) {
        const int kk = p << 5;
        const unsigned as = sbase + p*STGB, bs = sbase + 3*STGB + p*STGB;
        cpa16(as + o0, aS0 + kk); cpa16(as + o1, aS1 + kk);
        cpa16(bs + o0, bS0 + kk); cpa16(bs + o1, bS1 + kk);
        asm volatile("cp.async.commit_group;");
    }

    int st = 0, stp = 2;
    for (int kt = 0; kt < KT; kt++) {
        asm volatile("cp.async.wait_group 1;");
        __syncthreads();
        if (kt + 2 < KT) {
            const int kk = (kt + 2) << 5;
            const unsigned as = sbase + stp*STGB, bs = sbase + 3*STGB + stp*STGB;
            cpa16(as + o0, aS0 + kk); cpa16(as + o1, aS1 + kk);
            cpa16(bs + o0, bS0 + kk); cpa16(bs + o1, bS1 + kk);
        }
        asm volatile("cp.async.commit_group;");

        const unsigned aB = aF + st * STGB;
        const unsigned bB = bF + st * STGB;
#pragma unroll
        for (int ks = 0; ks < 2; ks++) {
            unsigned afr[4][4], bfr[4][2];
#pragma unroll
            for (int mf = 0; mf < 4; mf++)
                ldsm4(afr[mf], aB + mf * (16*PADK*2) + ks * 32);
#pragma unroll
            for (int p = 0; p < 2; p++) {
                unsigned r[4];
                ldsm4(r, bB + p * (16*PADK*2) + ks * 32);
                bfr[2*p][0] = r[0]; bfr[2*p][1] = r[1];
                bfr[2*p+1][0] = r[2]; bfr[2*p+1][1] = r[3];
            }
#pragma unroll
            for (int mf = 0; mf < 4; mf++)
#pragma unroll
                for (int nf = 0; nf < 4; nf++) {
                    asm volatile(
                        "mma.sync.aligned.m16n8k16.row.col.f32.bf16.bf16.f32 "
                        "{%0,%1,%2,%3},{%4,%5,%6,%7},{%8,%9},{%0,%1,%2,%3};"
                        : "+f"(acc[mf][nf][0]), "+f"(acc[mf][nf][1]),
                          "+f"(acc[mf][nf][2]), "+f"(acc[mf][nf][3])
                        : "r"(afr[mf][0]), "r"(afr[mf][1]), "r"(afr[mf][2]), "r"(afr[mf][3]),
                          "r"(bfr[nf][0]), "r"(bfr[nf][1]));
                }
        }
        st = (st == 2) ? 0 : st + 1;
        stp = (stp == 2) ? 0 : stp + 1;
    }

#pragma unroll
    for (int mf = 0; mf < 4; mf++)
#pragma unroll
        for (int rr = 0; rr < 2; rr++) {
            const int m = m0 + wm*64 + mf*16 + g + rr*8;
#pragma unroll
            for (int nf = 0; nf < 4; nf++) {
                const int n = n0 + wn*32 + nf*8 + 2*tig;
                if (n < N)     atomicAdd(&C[(size_t)m*ldc + n],     acc[mf][nf][rr*2]);
                if (n + 1 < N) atomicAdd(&C[(size_t)m*ldc + n + 1], acc[mf][nf][rr*2+1]);
            }
        }
}

// ---------------- small kernels ----------------
__global__ void assemble_x(const int* __restrict__ w, const float* __restrict__ emb,
                           const float* __restrict__ db)
{
    const int b = blockIdx.x, tid = threadIdx.x;
    const int wi = w[b];
    gb_x[b*2080 + tid]       = __float2bfloat16(emb[(size_t)wi*HH + tid]);
    gb_x[b*2080 + 256 + tid] = __float2bfloat16(emb[(size_t)wi*HH + 256 + tid]);
    if (tid < 32) gb_x[b*2080 + 2048 + tid] = __float2bfloat16(db[b*32 + tid]);
}

__global__ __launch_bounds__(256)
void ctx_k(const int* __restrict__ idu, const int* __restrict__ idb,
           const int* __restrict__ idp)
{
    const int b = blockIdx.x, e = blockIdx.y, tid = threadIdx.x;
    const bf16* enc; const int* ids; int T, soff;
    if (e == 0)      { enc = gb_usdx; ids = idu; T = TU; soff = 0; }
    else if (e == 1) { enc = gb_bspn; ids = idb; T = TB; soff = Bsz*TU; }
    else             { enc = gb_pv;   ids = idp; T = TP; soff = Bsz*(TU+TB); }

    __shared__ float a[TU];
    __shared__ float red[8];

    float s = -3.4e38f;
    if (tid < T) {
        s = g_scores[soff + b*T + tid];
        if (ids[b*T + tid] == 0) s = NEGV;
    }
    float v = s;
#pragma unroll
    for (int o = 16; o; o >>= 1) v = fmaxf(v, __shfl_xor_sync(~0u, v, o));
    if ((tid & 31) == 0) red[tid >> 5] = v;
    __syncthreads();
    float mx = red[0];
#pragma unroll
    for (int i = 1; i < 8; i++) mx = fmaxf(mx, red[i]);
    __syncthreads();

    const float ex = (tid < T) ? __expf(s - mx) : 0.f;
    v = ex;
#pragma unroll
    for (int o = 16; o; o >>= 1) v += __shfl_xor_sync(~0u, v, o);
    if ((tid & 31) == 0) red[tid >> 5] = v;
    __syncthreads();
    float sum = 0.f;
#pragma unroll
    for (int i = 0; i < 8; i++) sum += red[i];
    if (tid < T) a[tid] = ex / sum;
    __syncthreads();

    const unsigned* er32 = (const unsigned*)(enc + (size_t)b * T * HH);
    float ax = 0.f, ay = 0.f;
#pragma unroll 4
    for (int t = 0; t < T; t++) {
        const float at = a[t];
        const unsigned u = er32[t*256 + tid];
        const float2 f = __bfloat1622float2(*(const __nv_bfloat162*)&u);
        ax += at * f.x; ay += at * f.y;
    }
    const __nv_bfloat162 r2 = __floats2bfloat162_rn(ax, ay);
    *(unsigned*)(gb_x + b*2080 + 512 + e*HH + 2*tid) = *(const unsigned*)&r2;
}

__global__ void gate_k(const float* __restrict__ h0, const float* __restrict__ bih,
                       const float* __restrict__ bhh)
{
    const int i = blockIdx.x * 256 + threadIdx.x;
    const int b = i >> 9, h = i & (HH - 1);
    const float ir  = g_gi[b*1536 + h]        + bih[h];
    const float hr  = g_gh[b*1536 + h]        + bhh[h];
    const float iz  = g_gi[b*1536 + 512 + h]  + bih[512 + h];
    const float hz  = g_gh[b*1536 + 512 + h]  + bhh[512 + h];
    const float in_ = g_gi[b*1536 + 1024 + h] + bih[1024 + h];
    const float hn  = g_gh[b*1536 + 1024 + h] + bhh[1024 + h];
    const float r = 1.f / (1.f + __expf(-(ir + hr)));
    const float z = 1.f / (1.f + __expf(-(iz + hz)));
    const float n = tanh_fast(in_ + r * hn);
    const float hv = (1.f - z) * n + z * h0[i];
    g_hnew[i] = hv;
    gb_hnew[i] = __float2bfloat16(hv);
}

__global__ __launch_bounds__(256)
void final_k(const int* __restrict__ idb, const int* __restrict__ nounk,
             float* __restrict__ out)
{
    const int b = blockIdx.x, tid = threadIdx.x;
    __shared__ float cps[VV + TB];
    __shared__ float add2[VOOVc - VV];
    __shared__ float red[8];

    for (int i = tid; i < VV + TB; i += 256) cps[i] = 0.f;
    for (int i = tid; i < VOOVc - VV; i += 256) add2[i] = 0.f;
    __syncthreads();

    if (tid < TB) {
        float cr = g_cpraw[b*TB + tid];
        if (idb[b*TB + tid] == 0) cr = NEGV;
        const int nk = nounk[b*TB + tid];
        const int col = (nk < VV) ? nk : (VV + tid);
        atomicAdd(&cps[col], cr);
    }
    __syncthreads();

    const float* gb = g_gen + (size_t)b * VV;
    float mx = -3.4e38f;
    for (int i = tid; i < VV; i += 256)       mx = fmaxf(mx, gb[i]);
    for (int i = tid; i < VV + TB; i += 256)  mx = fmaxf(mx, cps[i]);
    float v = mx;
#pragma unroll
    for (int o = 16; o; o >>= 1) v = fmaxf(v, __shfl_xor_sync(~0u, v, o));
    if ((tid & 31) == 0) red[tid >> 5] = v;
    __syncthreads();
    mx = red[0];
#pragma unroll
    for (int i = 1; i < 8; i++) mx = fmaxf(mx, red[i]);
    __syncthreads();

    float se = 0.f;
    for (int i = tid; i < VV; i += 256)       se += expf(gb[i] - mx);
    for (int i = tid; i < VV + TB; i += 256)  se += expf(cps[i] - mx);
    v = se;
#pragma unroll
    for (int o = 16; o; o >>= 1) v += __shfl_xor_sync(~0u, v, o);
    if ((tid & 31) == 0) red[tid >> 5] = v;
    __syncthreads();
    se = 0.f;
#pragma unroll
    for (int i = 0; i < 8; i++) se += red[i];
    const float lz = mx + logf(se);

    float* ob = out + (size_t)b * VOOVc;
    for (int i = tid; i < VV; i += 256) {
        const float ga = gb[i] - lz, cc = cps[i] - lz;
        const float m2 = fmaxf(ga, cc);
        ob[i] = m2 + log1pf(expf(fminf(ga, cc) - m2));
    }
    if (tid < TB) {
        const int nk = nounk[b*TB + tid];
        if (nk >= VV) atomicAdd(&add2[nk - VV], expf(cps[VV + tid] - lz));
    }
    __syncthreads();
    for (int i = tid; i < VOOVc - VV; i += 256) {
        const float a2 = add2[i];
        ob[VV + i] = (a2 > 0.f) ? logf(fmaxf(a2, 1e-38f)) : NEGV;
    }
}

// ---------------- launcher ----------------
extern "C" void kernel_launch(void* const* d_in, const int* in_sizes, int n_in,
                              void* d_out, int out_size)
{
    (void)in_sizes; (void)n_in; (void)out_size;
    const int*   w     = (const int*)  d_in[0];
    const float* h0    = (const float*)d_in[1];
    const float* usdx  = (const float*)d_in[2];
    const float* bspn  = (const float*)d_in[3];
    const float* pv    = (const float*)d_in[4];
    const float* db    = (const float*)d_in[5];
    const int*   idu   = (const int*)  d_in[6];
    const int*   idb   = (const int*)  d_in[7];
    const int*   idp   = (const int*)  d_in[8];
    const int*   nounk = (const int*)  d_in[9];
    const float* emb   = (const float*)d_in[11];
    const float* attnW = (const float*)d_in[12];
    const float* attnb = (const float*)d_in[13];
    const float* vw    = (const float*)d_in[14];
    const float* Wc    = (const float*)d_in[15];
    const float* Wcb   = (const float*)d_in[16];
    const float* Wg    = (const float*)d_in[17];
    const float* Wgb   = (const float*)d_in[18];
    const float* Wih   = (const float*)d_in[19];
    const float* Whh   = (const float*)d_in[20];
    const float* bih   = (const float*)d_in[21];
    const float* bhh   = (const float*)d_in[22];
    float* out = (float*)d_out;

    float *q, *sc, *gi, *gh, *hn, *gen, *cpr;
    bf16 *bU, *bB, *bP, *bAW, *bWc, *bWg, *bWih, *bWhh, *bH0, *bX, *bHn;
    cudaGetSymbolAddress((void**)&q,   g_q);
    cudaGetSymbolAddress((void**)&sc,  g_scores);
    cudaGetSymbolAddress((void**)&gi,  g_gi);
    cudaGetSymbolAddress((void**)&gh,  g_gh);
    cudaGetSymbolAddress((void**)&hn,  g_hnew);
    cudaGetSymbolAddress((void**)&gen, g_gen);
    cudaGetSymbolAddress((void**)&cpr, g_cpraw);
    cudaGetSymbolAddress((void**)&bU,  gb_usdx);
    cudaGetSymbolAddress((void**)&bB,  gb_bspn);
    cudaGetSymbolAddress((void**)&bP,  gb_pv);
    cudaGetSymbolAddress((void**)&bAW, gb_attnW);
    cudaGetSymbolAddress((void**)&bWc, gb_Wc);
    cudaGetSymbolAddress((void**)&bWg, gb_Wg);
    cudaGetSymbolAddress((void**)&bWih,gb_Wih);
    cudaGetSymbolAddress((void**)&bWhh,gb_Whh);
    cudaGetSymbolAddress((void**)&bH0, gb_h0);
    cudaGetSymbolAddress((void**)&bX,  gb_x);
    cudaGetSymbolAddress((void**)&bHn, gb_hnew);

    cudaFuncSetAttribute(mma_gemm2,   cudaFuncAttributeMaxDynamicSharedMemorySize, SMEMB);
    cudaFuncSetAttribute(score_batch, cudaFuncAttributeMaxDynamicSharedMemorySize, SSMEM);
    cudaFuncSetAttribute(score_gen,   cudaFuncAttributeMaxDynamicSharedMemorySize, SSMEM);

    // 1. all conversions + inits
    megacvt<<<1184, 256>>>(usdx, bspn, pv, attnW, Wc, Wg, Wih, Whh, h0, attnb, Wgb);

    // 2. assemble x
    assemble_x<<<Bsz, 256>>>(w, emb, db);

    // 3. q += h0 @ W1^T  (split-K x4, q pre-init to attn_b)
    mma_gemm2<<<dim3(4, 1, 4), 256, SMEMB>>>(bH0, HH, bAW, 2*HH, q, HH, HH, 128);

    // 4. fused attention logits (batched, K-tile 64)
    score_batch<<<dim3(4, 448), 256, SSMEM>>>(vw);

    // 5. softmax + ctx into gb_x
    ctx_k<<<dim3(Bsz, 3), 256>>>(idu, idb, idp);

    // 6. GRU projections (split-K, biases folded into gate)
    mma_gemm2<<<dim3(12, 1, 5), 256, SMEMB>>>(bX, 2080, bWih, 2080, gi, 1536, 1536, 416);
    mma_gemm2<<<dim3(12, 1, 2), 256, SMEMB>>>(bH0, HH, bWhh, HH, gh, 1536, 1536, 256);
    gate_k<<<Bsz*HH/256, 256>>>(h0, bih, bhh);

    // 7. gen += hnew @ Wg^T  (split-K x2, gen pre-init to Wgen_b)
    mma_gemm2<<<dim3(24, 1, 2), 256, SMEMB>>>(bHn, HH, bWg, HH, gen, VV, VV, 256);

    // 8. cp_raw[b,t] = sum_h hnew[b,h]*tanh(bspn@Wc^T + Wcb)  (K-tile 64)
    score_gen<<<dim3(4, 128), 256, SSMEM>>>(bB, HH, bWc, HH, HH, Wcb, 0, hn, HH, cpr, TB);

    // 9. joint log-softmax + copy-scatter + logaddexp + OOV
    final_k<<<Bsz, 256>>>(idb, nounk, out);
}

// round 13
// speedup vs baseline: 1.2276x; 1.2276x over previous
#include <cuda_runtime.h>
#include <cuda_bf16.h>
#include <cstdint>

#define NEGV  (-1e20f)
#define Bsz   128
#define TU    256
#define TB    128
#define TP    64
#define HH    512
#define VV    3000
#define VOOVc 3400

typedef __nv_bfloat16 bf16;

// ---------------- fp32 scratch ----------------
__device__ float g_q[Bsz*HH];
__device__ float g_scores[Bsz*(TU+TB+TP)];
__device__ float g_gi[Bsz*1536];
__device__ float g_gh[Bsz*1536];
__device__ float g_hnew[Bsz*HH];
__device__ float g_gen[Bsz*VV];
__device__ float g_cpraw[Bsz*TB];

// ---------------- bf16 scratch ----------------
__device__ __align__(16) bf16 gb_usdx[Bsz*TU*HH];
__device__ __align__(16) bf16 gb_bspn[Bsz*TB*HH];
__device__ __align__(16) bf16 gb_pv  [Bsz*TP*HH];
__device__ __align__(16) bf16 gb_attnW[HH*2*HH];
__device__ __align__(16) bf16 gb_Wc  [HH*HH];
__device__ __align__(16) bf16 gb_Wg  [3072*HH];
__device__ __align__(16) bf16 gb_Wih [1536*2080];
__device__ __align__(16) bf16 gb_Whh [1536*HH];
__device__ __align__(16) bf16 gb_h0  [Bsz*HH];
__device__ __align__(16) bf16 gb_x   [Bsz*2080];
__device__ __align__(16) bf16 gb_hnew[Bsz*HH];

// ==================== helpers ====================
__device__ __forceinline__ void cpa16(unsigned d, const void* s) {
    asm volatile("cp.async.cg.shared.global [%0], [%1], 16;" :: "r"(d), "l"(s));
}
__device__ __forceinline__ void ldsm4(unsigned* r, unsigned a) {
    asm volatile("ldmatrix.sync.aligned.m8n8.x4.shared.b16 {%0,%1,%2,%3}, [%4];"
                 : "=r"(r[0]), "=r"(r[1]), "=r"(r[2]), "=r"(r[3]) : "r"(a));
}
__device__ __forceinline__ float tanh_fast(float x) {
    float y;
    asm("tanh.approx.f32 %0, %1;" : "=f"(y) : "f"(x));
    return y;
}

// ==================== megacvt ====================
#define C_USDX  (Bsz*TU*HH/4)
#define C_BSPN  (C_USDX + Bsz*TB*HH/4)
#define C_PV    (C_BSPN + Bsz*TP*HH/4)
#define C_AW    (C_PV   + HH*2*HH/4)
#define C_WC    (C_AW   + HH*HH/4)
#define C_WG    (C_WC   + 3072*HH/4)
#define C_WIH   (C_WG   + 1536*2080/4)
#define C_WHH   (C_WIH  + 1536*HH/4)
#define C_H0    (C_WHH  + Bsz*HH/4)
#define C_Q     (C_H0   + Bsz*HH/4)
#define C_GEN   (C_Q    + Bsz*VV/4)
#define C_ZS    (C_GEN  + Bsz*(TU+TB+TP)/4)
#define C_ZC    (C_ZS   + Bsz*TB/4)
#define C_ZGI   (C_ZC   + Bsz*1536/4)
#define C_ZGH   (C_ZGI  + Bsz*1536/4)

__device__ __forceinline__ void cv4(const float* __restrict__ s, bf16* __restrict__ d, int i)
{
    const float4 v = *(const float4*)(s + 4*(size_t)i);
    __nv_bfloat162 lo = __floats2bfloat162_rn(v.x, v.y);
    __nv_bfloat162 hi = __floats2bfloat162_rn(v.z, v.w);
    *(uint2*)(d + 4*(size_t)i) = make_uint2(*(unsigned*)&lo, *(unsigned*)&hi);
}

__global__ __launch_bounds__(256)
void megacvt(const float* __restrict__ usdx, const float* __restrict__ bspn,
             const float* __restrict__ pv,   const float* __restrict__ aw,
             const float* __restrict__ wc,   const float* __restrict__ wg,
             const float* __restrict__ wih,  const float* __restrict__ whh,
             const float* __restrict__ h0,   const float* __restrict__ attnb,
             const float* __restrict__ wgb)
{
    const int stride = gridDim.x * blockDim.x;
    for (int i = blockIdx.x * blockDim.x + threadIdx.x; i < C_ZGH; i += stride) {
        if (i < C_USDX)      cv4(usdx, gb_usdx, i);
        else if (i < C_BSPN) cv4(bspn, gb_bspn, i - C_USDX);
        else if (i < C_PV)   cv4(pv,   gb_pv,   i - C_BSPN);
        else if (i < C_AW)   cv4(aw,   gb_attnW,i - C_PV);
        else if (i < C_WC)   cv4(wc,   gb_Wc,   i - C_AW);
        else if (i < C_WG) {
            const int j = i - C_WC;
            if (4*j < VV*HH) cv4(wg, gb_Wg, j);
            else *(uint2*)(gb_Wg + 4*(size_t)j) = make_uint2(0u, 0u);
        }
        else if (i < C_WIH)  cv4(wih, gb_Wih, i - C_WG);
        else if (i < C_WHH)  cv4(whh, gb_Whh, i - C_WIH);
        else if (i < C_H0)   cv4(h0,  gb_h0,  i - C_WHH);
        else if (i < C_Q) {
            const int j = (i - C_H0) * 4;
            *(float4*)(g_q + j) = *(const float4*)(attnb + (j & (HH-1)));
        }
        else if (i < C_GEN) {
            const int j = (i - C_Q) * 4;
            *(float4*)(g_gen + j) = *(const float4*)(wgb + (j % VV));
        }
        else if (i < C_ZS)  *(float4*)(g_scores + (i - C_GEN)*4) = make_float4(0,0,0,0);
        else if (i < C_ZC)  *(float4*)(g_cpraw  + (i - C_ZS)*4)  = make_float4(0,0,0,0);
        else if (i < C_ZGI) *(float4*)(g_gi     + (i - C_ZC)*4)  = make_float4(0,0,0,0);
        else                *(float4*)(g_gh     + (i - C_ZGI)*4) = make_float4(0,0,0,0);
    }
}

// =====================================================================
// Unified HMMA GEMM core, K-tile 32, FOUR-stage cp.async, ldmatrix.
// Tile 128x128, K%32==0 (KT may be < 3: prologue guarded).
// EPI==1: sOut[m] += sum_n dvec[b,n]*tanh(acc+qadd[b,n]), b=m/T  (N%128==0)
// EPI==2: atomicAdd(C[m,n], acc)   (n<N guarded)
// =====================================================================
#define PADK 40
#define STGB (128*PADK*2)      // 10240 B per stage per matrix
#define NSTG 4
#define SMEMB (2*NSTG*STGB)    // 81920 B

template<int EPI>
__device__ __forceinline__ void gcore(
    const bf16* __restrict__ A, int lda,
    const bf16* __restrict__ Bw, int ldb,
    float* __restrict__ C, int ldc,
    int N, int K, int m0, int n0,
    const float* __restrict__ qadd, int qstride,
    const float* __restrict__ dvec, int dstride,
    float* __restrict__ sOut, int T, bf16* smem)
{
    const int tid = threadIdx.x, lane = tid & 31, wid = tid >> 5;
    const int wm = wid >> 2, wn = wid & 3;
    const int g = lane >> 2, tig = lane & 3;
    const unsigned sbase = (unsigned)__cvta_generic_to_shared(smem);

    const int crow = tid >> 2, ci = tid & 3;
    const bf16* aS0 = A  + (size_t)(m0 + crow) * lda + ci*8;
    const bf16* aS1 = aS0 + (size_t)64 * lda;
    const bf16* bS0 = Bw + (size_t)(n0 + crow) * ldb + ci*8;
    const bf16* bS1 = bS0 + (size_t)64 * ldb;
    const unsigned o0 = (crow * PADK + ci*8) * 2;
    const unsigned o1 = o0 + 64*PADK*2;

    const unsigned aF = sbase + ((wm*64 + (lane&15)) * PADK + ((lane>>4)*8)) * 2;
    const unsigned bF = sbase + NSTG*STGB +
        ((wn*32 + ((lane>>4)*8) + (lane&7)) * PADK + (((lane>>3)&1)*8)) * 2;

    float acc[4][4][4];
#pragma unroll
    for (int i = 0; i < 4; i++)
#pragma unroll
        for (int j = 0; j < 4; j++)
#pragma unroll
            for (int c = 0; c < 4; c++) acc[i][j][c] = 0.f;

    const int KT = K >> 5;

    // prologue: stages 0..2 (guarded for small KT)
#pragma unroll
    for (int p = 0; p < NSTG-1; p++) {
        if (p < KT) {
            const int kk = p << 5;
            const unsigned as = sbase + p*STGB, bs = sbase + NSTG*STGB + p*STGB;
            cpa16(as + o0, aS0 + kk); cpa16(as + o1, aS1 + kk);
            cpa16(bs + o0, bS0 + kk); cpa16(bs + o1, bS1 + kk);
        }
        asm volatile("cp.async.commit_group;");
    }

    for (int kt = 0; kt < KT; kt++) {
        asm volatile("cp.async.wait_group %0;" :: "n"(NSTG-2));
        __syncthreads();
        if (kt + NSTG - 1 < KT) {
            const int kk = (kt + NSTG - 1) << 5;
            const int sp = (kt + NSTG - 1) & (NSTG-1);
            const unsigned as = sbase + sp*STGB, bs = sbase + NSTG*STGB + sp*STGB;
            cpa16(as + o0, aS0 + kk); cpa16(as + o1, aS1 + kk);
            cpa16(bs + o0, bS0 + kk); cpa16(bs + o1, bS1 + kk);
        }
        asm volatile("cp.async.commit_group;");

        const int st = kt & (NSTG-1);
        const unsigned aB = aF + st * STGB;
        const unsigned bB = bF + st * STGB;
#pragma unroll
        for (int ks = 0; ks < 2; ks++) {
            unsigned afr[4][4], bfr[4][2];
#pragma unroll
            for (int mf = 0; mf < 4; mf++)
                ldsm4(afr[mf], aB + mf * (16*PADK*2) + ks * 32);
#pragma unroll
            for (int p = 0; p < 2; p++) {
                unsigned r[4];
                ldsm4(r, bB + p * (16*PADK*2) + ks * 32);
                bfr[2*p][0] = r[0]; bfr[2*p][1] = r[1];
                bfr[2*p+1][0] = r[2]; bfr[2*p+1][1] = r[3];
            }
#pragma unroll
            for (int mf = 0; mf < 4; mf++)
#pragma unroll
                for (int nf = 0; nf < 4; nf++) {
                    asm volatile(
                        "mma.sync.aligned.m16n8k16.row.col.f32.bf16.bf16.f32 "
                        "{%0,%1,%2,%3},{%4,%5,%6,%7},{%8,%9},{%0,%1,%2,%3};"
                        : "+f"(acc[mf][nf][0]), "+f"(acc[mf][nf][1]),
                          "+f"(acc[mf][nf][2]), "+f"(acc[mf][nf][3])
                        : "r"(afr[mf][0]), "r"(afr[mf][1]), "r"(afr[mf][2]), "r"(afr[mf][3]),
                          "r"(bfr[nf][0]), "r"(bfr[nf][1]));
                }
        }
    }

    if (EPI == 2) {
#pragma unroll
        for (int mf = 0; mf < 4; mf++)
#pragma unroll
            for (int rr = 0; rr < 2; rr++) {
                const int m = m0 + wm*64 + mf*16 + g + rr*8;
#pragma unroll
                for (int nf = 0; nf < 4; nf++) {
                    const int n = n0 + wn*32 + nf*8 + 2*tig;
                    if (n < N)     atomicAdd(&C[(size_t)m*ldc + n],     acc[mf][nf][rr*2]);
                    if (n + 1 < N) atomicAdd(&C[(size_t)m*ldc + n + 1], acc[mf][nf][rr*2+1]);
                }
            }
    } else {
#pragma unroll
        for (int mf = 0; mf < 4; mf++)
#pragma unroll
            for (int rr = 0; rr < 2; rr++) {
                const int m = m0 + wm*64 + mf*16 + g + rr*8;
                const int b = m / T;
                const float* q  = qadd + (size_t)b * qstride;
                const float* dv = dvec + (size_t)b * dstride;
                float s = 0.f;
#pragma unroll
                for (int nf = 0; nf < 4; nf++) {
                    const int n = n0 + wn*32 + nf*8 + 2*tig;
                    s += dv[n]   * tanh_fast(acc[mf][nf][rr*2]   + q[n]);
                    s += dv[n+1] * tanh_fast(acc[mf][nf][rr*2+1] + q[n+1]);
                }
                s += __shfl_xor_sync(0xffffffffu, s, 1);
                s += __shfl_xor_sync(0xffffffffu, s, 2);
                if (tig == 0) atomicAdd(&sOut[m], s);
            }
    }
}

// score batch: by<448 -> fused attention logits; by>=448 -> gh GEMM tiles
__global__ __launch_bounds__(256, 2)
void score_batch(const float* __restrict__ vw)
{
    extern __shared__ bf16 smem_sb[];
    const int by = blockIdx.y;
    if (by < 448) {
        const bf16* A; float* sOut; int T, m0;
        if (by < 256)      { A = gb_usdx; sOut = g_scores;               T = TU; m0 = by*128; }
        else if (by < 384) { A = gb_bspn; sOut = g_scores + Bsz*TU;      T = TB; m0 = (by-256)*128; }
        else               { A = gb_pv;   sOut = g_scores + Bsz*(TU+TB); T = TP; m0 = (by-384)*128; }
        gcore<1>(A, HH, gb_attnW + HH, 2*HH, nullptr, 0, HH, HH,
                 m0, blockIdx.x * 128, g_q, HH, vw, 0, sOut, T, smem_sb);
    } else {
        // gh = h0 @ Whh^T : 12 n-tiles of 128, full K=512
        const int t = (by - 448) * 4 + blockIdx.x;
        if (t < 12)
            gcore<2>(gb_h0, HH, gb_Whh, HH, g_gh, 1536, 1536, HH,
                     0, t * 128, nullptr, 0, nullptr, 0, nullptr, 1, smem_sb);
    }
}

// generic EPI1 wrapper (cp_raw)
__global__ __launch_bounds__(256, 2)
void gk_score(const bf16* __restrict__ A, int lda,
              const bf16* __restrict__ Bw, int ldb, int K,
              const float* __restrict__ qadd, int qstride,
              const float* __restrict__ dvec, int dstride,
              float* __restrict__ sOut, int T)
{
    extern __shared__ bf16 smem_sg[];
    gcore<1>(A, lda, Bw, ldb, nullptr, 0, 0, K, blockIdx.y * 128, blockIdx.x * 128,
             qadd, qstride, dvec, dstride, sOut, T, smem_sg);
}

// generic EPI2 wrapper (split-K dense atomic)
__global__ __launch_bounds__(256, 2)
void gk_atomic(const bf16* __restrict__ A, int lda,
               const bf16* __restrict__ Bw, int ldb,
               float* __restrict__ C, int ldc, int N, int K)
{
    extern __shared__ bf16 smem_ga[];
    const int koff = blockIdx.z * K;
    gcore<2>(A + koff, lda, Bw + koff, ldb, C, ldc, N, K,
             blockIdx.y * 128, blockIdx.x * 128,
             nullptr, 0, nullptr, 0, nullptr, 1, smem_ga);
}

// ---------------- small kernels ----------------
__global__ void assemble_x(const int* __restrict__ w, const float* __restrict__ emb,
                           const float* __restrict__ db)
{
    const int b = blockIdx.x, tid = threadIdx.x;
    const int wi = w[b];
    gb_x[b*2080 + tid]       = __float2bfloat16(emb[(size_t)wi*HH + tid]);
    gb_x[b*2080 + 256 + tid] = __float2bfloat16(emb[(size_t)wi*HH + 256 + tid]);
    if (tid < 32) gb_x[b*2080 + 2048 + tid] = __float2bfloat16(db[b*32 + tid]);
}

__global__ __launch_bounds__(256)
void ctx_k(const int* __restrict__ idu, const int* __restrict__ idb,
           const int* __restrict__ idp)
{
    const int b = blockIdx.x, e = blockIdx.y, tid = threadIdx.x;
    const bf16* enc; const int* ids; int T, soff;
    if (e == 0)      { enc = gb_usdx; ids = idu; T = TU; soff = 0; }
    else if (e == 1) { enc = gb_bspn; ids = idb; T = TB; soff = Bsz*TU; }
    else             { enc = gb_pv;   ids = idp; T = TP; soff = Bsz*(TU+TB); }

    __shared__ float a[TU];
    __shared__ float red[8];

    float s = -3.4e38f;
    if (tid < T) {
        s = g_scores[soff + b*T + tid];
        if (ids[b*T + tid] == 0) s = NEGV;
    }
    float v = s;
#pragma unroll
    for (int o = 16; o; o >>= 1) v = fmaxf(v, __shfl_xor_sync(~0u, v, o));
    if ((tid & 31) == 0) red[tid >> 5] = v;
    __syncthreads();
    float mx = red[0];
#pragma unroll
    for (int i = 1; i < 8; i++) mx = fmaxf(mx, red[i]);
    __syncthreads();

    const float ex = (tid < T) ? __expf(s - mx) : 0.f;
    v = ex;
#pragma unroll
    for (int o = 16; o; o >>= 1) v += __shfl_xor_sync(~0u, v, o);
    if ((tid & 31) == 0) red[tid >> 5] = v;
    __syncthreads();
    float sum = 0.f;
#pragma unroll
    for (int i = 0; i < 8; i++) sum += red[i];
    if (tid < T) a[tid] = ex / sum;
    __syncthreads();

    const unsigned* er32 = (const unsigned*)(enc + (size_t)b * T * HH);
    float ax = 0.f, ay = 0.f;
#pragma unroll 8
    for (int t = 0; t < T; t++) {
        const float at = a[t];
        const unsigned u = er32[t*256 + tid];
        const float2 f = __bfloat1622float2(*(const __nv_bfloat162*)&u);
        ax += at * f.x; ay += at * f.y;
    }
    const __nv_bfloat162 r2 = __floats2bfloat162_rn(ax, ay);
    *(unsigned*)(gb_x + b*2080 + 512 + e*HH + 2*tid) = *(const unsigned*)&r2;
}

__global__ void gate_k(const float* __restrict__ h0, const float* __restrict__ bih,
                       const float* __restrict__ bhh)
{
    const int i = blockIdx.x * 256 + threadIdx.x;
    const int b = i >> 9, h = i & (HH - 1);
    const float ir  = g_gi[b*1536 + h]        + bih[h];
    const float hr  = g_gh[b*1536 + h]        + bhh[h];
    const float iz  = g_gi[b*1536 + 512 + h]  + bih[512 + h];
    const float hz  = g_gh[b*1536 + 512 + h]  + bhh[512 + h];
    const float in_ = g_gi[b*1536 + 1024 + h] + bih[1024 + h];
    const float hn  = g_gh[b*1536 + 1024 + h] + bhh[1024 + h];
    const float r = 1.f / (1.f + __expf(-(ir + hr)));
    const float z = 1.f / (1.f + __expf(-(iz + hz)));
    const float n = tanh_fast(in_ + r * hn);
    const float hv = (1.f - z) * n + z * h0[i];
    g_hnew[i] = hv;
    gb_hnew[i] = __float2bfloat16(hv);
}

__global__ __launch_bounds__(256)
void final_k(const int* __restrict__ idb, const int* __restrict__ nounk,
             float* __restrict__ out)
{
    const int b = blockIdx.x, tid = threadIdx.x;
    __shared__ float cps[VV + TB];
    __shared__ float add2[VOOVc - VV];
    __shared__ float red[8];

    for (int i = tid; i < VV + TB; i += 256) cps[i] = 0.f;
    for (int i = tid; i < VOOVc - VV; i += 256) add2[i] = 0.f;
    __syncthreads();

    if (tid < TB) {
        float cr = g_cpraw[b*TB + tid];
        if (idb[b*TB + tid] == 0) cr = NEGV;
        const int nk = nounk[b*TB + tid];
        const int col = (nk < VV) ? nk : (VV + tid);
        atomicAdd(&cps[col], cr);
    }
    __syncthreads();

    const float* gb = g_gen + (size_t)b * VV;
    float mx = -3.4e38f;
    for (int i = tid; i < VV; i += 256)       mx = fmaxf(mx, gb[i]);
    for (int i = tid; i < VV + TB; i += 256)  mx = fmaxf(mx, cps[i]);
    float v = mx;
#pragma unroll
    for (int o = 16; o; o >>= 1) v = fmaxf(v, __shfl_xor_sync(~0u, v, o));
    if ((tid & 31) == 0) red[tid >> 5] = v;
    __syncthreads();
    mx = red[0];
#pragma unroll
    for (int i = 1; i < 8; i++) mx = fmaxf(mx, red[i]);
    __syncthreads();

    float se = 0.f;
    for (int i = tid; i < VV; i += 256)       se += expf(gb[i] - mx);
    for (int i = tid; i < VV + TB; i += 256)  se += expf(cps[i] - mx);
    v = se;
#pragma unroll
    for (int o = 16; o; o >>= 1) v += __shfl_xor_sync(~0u, v, o);
    if ((tid & 31) == 0) red[tid >> 5] = v;
    __syncthreads();
    se = 0.f;
#pragma unroll
    for (int i = 0; i < 8; i++) se += red[i];
    const float lz = mx + logf(se);

    float* ob = out + (size_t)b * VOOVc;
    for (int i = tid; i < VV; i += 256) {
        const float ga = gb[i] - lz, cc = cps[i] - lz;
        const float m2 = fmaxf(ga, cc);
        ob[i] = m2 + log1pf(expf(fminf(ga, cc) - m2));
    }
    if (tid < TB) {
        const int nk = nounk[b*TB + tid];
        if (nk >= VV) atomicAdd(&add2[nk - VV], expf(cps[VV + tid] - lz));
    }
    __syncthreads();
    for (int i = tid; i < VOOVc - VV; i += 256) {
        const float a2 = add2[i];
        ob[VV + i] = (a2 > 0.f) ? logf(fmaxf(a2, 1e-38f)) : NEGV;
    }
}

// ---------------- launcher ----------------
extern "C" void kernel_launch(void* const* d_in, const int* in_sizes, int n_in,
                              void* d_out, int out_size)
{
    (void)in_sizes; (void)n_in; (void)out_size;
    const int*   w     = (const int*)  d_in[0];
    const float* h0    = (const float*)d_in[1];
    const float* usdx  = (const float*)d_in[2];
    const float* bspn  = (const float*)d_in[3];
    const float* pv    = (const float*)d_in[4];
    const float* db    = (const float*)d_in[5];
    const int*   idu   = (const int*)  d_in[6];
    const int*   idb   = (const int*)  d_in[7];
    const int*   idp   = (const int*)  d_in[8];
    const int*   nounk = (const int*)  d_in[9];
    const float* emb   = (const float*)d_in[11];
    const float* attnW = (const float*)d_in[12];
    const float* attnb = (const float*)d_in[13];
    const float* vw    = (const float*)d_in[14];
    const float* Wc    = (const float*)d_in[15];
    const float* Wcb   = (const float*)d_in[16];
    const float* Wg    = (const float*)d_in[17];
    const float* Wgb   = (const float*)d_in[18];
    const float* Wih   = (const float*)d_in[19];
    const float* Whh   = (const float*)d_in[20];
    const float* bih   = (const float*)d_in[21];
    const float* bhh   = (const float*)d_in[22];
    float* out = (float*)d_out;

    float *q, *sc, *gi, *gh, *hn, *gen, *cpr;
    bf16 *bU, *bB, *bP, *bAW, *bWc, *bWg, *bWih, *bWhh, *bH0, *bX, *bHn;
    cudaGetSymbolAddress((void**)&q,   g_q);
    cudaGetSymbolAddress((void**)&sc,  g_scores);
    cudaGetSymbolAddress((void**)&gi,  g_gi);
    cudaGetSymbolAddress((void**)&gh,  g_gh);
    cudaGetSymbolAddress((void**)&hn,  g_hnew);
    cudaGetSymbolAddress((void**)&gen, g_gen);
    cudaGetSymbolAddress((void**)&cpr, g_cpraw);
    cudaGetSymbolAddress((void**)&bU,  gb_usdx);
    cudaGetSymbolAddress((void**)&bB,  gb_bspn);
    cudaGetSymbolAddress((void**)&bP,  gb_pv);
    cudaGetSymbolAddress((void**)&bAW, gb_attnW);
    cudaGetSymbolAddress((void**)&bWc, gb_Wc);
    cudaGetSymbolAddress((void**)&bWg, gb_Wg);
    cudaGetSymbolAddress((void**)&bWih,gb_Wih);
    cudaGetSymbolAddress((void**)&bWhh,gb_Whh);
    cudaGetSymbolAddress((void**)&bH0, gb_h0);
    cudaGetSymbolAddress((void**)&bX,  gb_x);
    cudaGetSymbolAddress((void**)&bHn, gb_hnew);

    cudaFuncSetAttribute(score_batch, cudaFuncAttributeMaxDynamicSharedMemorySize, SMEMB);
    cudaFuncSetAttribute(gk_score,    cudaFuncAttributeMaxDynamicSharedMemorySize, SMEMB);
    cudaFuncSetAttribute(gk_atomic,   cudaFuncAttributeMaxDynamicSharedMemorySize, SMEMB);

    // 1. all conversions + inits
    megacvt<<<1184, 256>>>(usdx, bspn, pv, attnW, Wc, Wg, Wih, Whh, h0, attnb, Wgb);

    // 2. assemble x
    assemble_x<<<Bsz, 256>>>(w, emb, db);

    // 3. q += h0 @ W1^T  (split-K x8, q pre-init to attn_b)
    gk_atomic<<<dim3(4, 1, 8), 256, SMEMB>>>(bH0, HH, bAW, 2*HH, q, HH, HH, 64);

    // 4. fused attention logits (batched) + gh GEMM absorbed (by 448..450)
    score_batch<<<dim3(4, 451), 256, SMEMB>>>(vw);

    // 5. softmax + ctx into gb_x
    ctx_k<<<dim3(Bsz, 3), 256>>>(idu, idb, idp);

    // 6. GRU input projection (split-K x13, biases folded into gate)
    gk_atomic<<<dim3(12, 1, 13), 256, SMEMB>>>(bX, 2080, bWih, 2080, gi, 1536, 1536, 160);
    gate_k<<<Bsz*HH/256, 256>>>(h0, bih, bhh);

    // 7. gen += hnew @ Wg^T  (split-K x8, gen pre-init to Wgen_b)
    gk_atomic<<<dim3(24, 1, 8), 256, SMEMB>>>(bHn, HH, bWg, HH, gen, VV, VV, 64);

    // 8. cp_raw[b,t] = sum_h hnew[b,h]*tanh(bspn@Wc^T + Wcb)
    gk_score<<<dim3(4, 128), 256, SMEMB>>>(bB, HH, bWc, HH, HH, Wcb, 0, hn, HH, cpr, TB);

    // 9. joint log-softmax + copy-scatter + logaddexp + OOV
    final_k<<<Bsz, 256>>>(idb, nounk, out);
}